// round 15
// baseline (speedup 1.0000x reference)
#include <cuda_runtime.h>
#include <cuda_bf16.h>
#include <math.h>
#include <stdint.h>

#define B_  4
#define T_  2048
#define D_  1024
#define H_  16
#define DH_ 64
#define M_  (B_*T_)      // 8192 rows
#define MAXREL 128
#define DD_ (D_*D_)

// ---------------- scratch (device globals; no allocs allowed) ----------------
__device__ __nv_bfloat16 g_xnh[M_*D_], g_xnl[M_*D_];     // LN output, split bf16
__device__ __nv_bfloat16 g_wh[4*DD_],  g_wl[4*DD_];      // Wq,Wk,Wv,Wo split
__device__ __nv_bfloat16 g_yh[M_*D_],  g_yl[M_*D_];      // attention output, split
__device__ __nv_bfloat16 g_qh[M_*D_],  g_ql[M_*D_];
__device__ __nv_bfloat16 g_kh[M_*D_],  g_kl[M_*D_];
__device__ __nv_bfloat16 g_vh[M_*D_],  g_vl[M_*D_];

// ---------------- helpers ----------------
__device__ __forceinline__ uint32_t bf2_pack(__nv_bfloat16 a, __nv_bfloat16 b)
{
    __nv_bfloat162 p = __halves2bfloat162(a, b);   // a -> low 16 bits
    return *reinterpret_cast<uint32_t*>(&p);
}

__device__ __forceinline__ void split2pack(float a, float b, uint32_t& hp, uint32_t& lp)
{
    __nv_bfloat16 ah = __float2bfloat16_rn(a), bh = __float2bfloat16_rn(b);
    __nv_bfloat16 al = __float2bfloat16_rn(a - __bfloat162float(ah));
    __nv_bfloat16 bl = __float2bfloat16_rn(b - __bfloat162float(bh));
    hp = bf2_pack(ah, bh);
    lp = bf2_pack(al, bl);
}

__device__ __forceinline__ void split4(const float* v, uint32_t& h01, uint32_t& h23,
                                       uint32_t& l01, uint32_t& l23)
{
    split2pack(v[0], v[1], h01, l01);
    split2pack(v[2], v[3], h23, l23);
}

__device__ __forceinline__ uint32_t sm_u32(const void* p)
{
    uint32_t a;
    asm("{ .reg .u64 t; cvta.to.shared.u64 t, %1; cvt.u32.u64 %0, t; }" : "=r"(a) : "l"(p));
    return a;
}

__device__ __forceinline__ void mma16816(float* d, const uint32_t* a, const uint32_t* b)
{
    asm volatile(
        "mma.sync.aligned.m16n8k16.row.col.f32.bf16.bf16.f32 "
        "{%0,%1,%2,%3}, {%4,%5,%6,%7}, {%8,%9}, {%0,%1,%2,%3};\n"
        : "+f"(d[0]), "+f"(d[1]), "+f"(d[2]), "+f"(d[3])
        : "r"(a[0]), "r"(a[1]), "r"(a[2]), "r"(a[3]), "r"(b[0]), "r"(b[1]));
}

#define CPA16(dst, src) asm volatile("cp.async.cg.shared.global [%0], [%1], 16;\n" :: "r"(dst), "l"(src))
#define CPA_COMMIT()    asm volatile("cp.async.commit_group;\n" ::)
#define CPA_WAIT1()     asm volatile("cp.async.wait_group 1;\n" ::)
#define CPA_WAIT0()     asm volatile("cp.async.wait_group 0;\n" ::)

#define LDSM4(R, a) asm volatile( \
    "ldmatrix.sync.aligned.m8n8.x4.shared.b16 {%0,%1,%2,%3}, [%4];" \
    : "=r"((R)[0]), "=r"((R)[1]), "=r"((R)[2]), "=r"((R)[3]) : "r"(a))
#define LDSM4T(R, a) asm volatile( \
    "ldmatrix.sync.aligned.m8n8.x4.trans.shared.b16 {%0,%1,%2,%3}, [%4];" \
    : "=r"((R)[0]), "=r"((R)[1]), "=r"((R)[2]), "=r"((R)[3]) : "r"(a))

#define SMEM_SWZ(o) ((uint32_t)(o) ^ ((((uint32_t)(o)) >> 3) & 0x70u))

// ---------------- LayerNorm: one block per row, writes split bf16 ------------
__global__ void ln_kernel(const float* __restrict__ x, const float* __restrict__ gamma,
                          const float* __restrict__ beta,
                          __nv_bfloat16* __restrict__ xnh, __nv_bfloat16* __restrict__ xnl)
{
    const int row = blockIdx.x;
    const int tid = threadIdx.x;
    const float4 v = *(const float4*)(x + (size_t)row*D_ + tid*4);
    float s  = v.x + v.y + v.z + v.w;
    float ss = v.x*v.x + v.y*v.y + v.z*v.z + v.w*v.w;
    #pragma unroll
    for (int off = 16; off; off >>= 1) {
        s  += __shfl_xor_sync(0xffffffffu, s,  off);
        ss += __shfl_xor_sync(0xffffffffu, ss, off);
    }
    __shared__ float sh_s[8], sh_ss[8];
    const int w = tid >> 5;
    if ((tid & 31) == 0) { sh_s[w] = s; sh_ss[w] = ss; }
    __syncthreads();
    float ts = 0.f, tss = 0.f;
    #pragma unroll
    for (int i = 0; i < 8; i++) { ts += sh_s[i]; tss += sh_ss[i]; }
    const float mu   = ts * (1.0f / D_);
    const float var  = tss * (1.0f / D_) - mu * mu;
    const float rstd = rsqrtf(var + 1e-5f);
    const float4 gv = *(const float4*)(gamma + tid*4);
    const float4 bv = *(const float4*)(beta  + tid*4);
    float o[4];
    o[0] = (v.x - mu) * rstd * gv.x + bv.x;
    o[1] = (v.y - mu) * rstd * gv.y + bv.y;
    o[2] = (v.z - mu) * rstd * gv.z + bv.z;
    o[3] = (v.w - mu) * rstd * gv.w + bv.w;
    uint32_t h01, h23, l01, l23;
    split4(o, h01, h23, l01, l23);
    *(uint2*)(xnh + (size_t)row*D_ + tid*4) = make_uint2(h01, h23);
    *(uint2*)(xnl + (size_t)row*D_ + tid*4) = make_uint2(l01, l23);
}

// ---------------- Weight split ----------------
__global__ void wsplit_kernel(const float* __restrict__ Wq, const float* __restrict__ Wk,
                              const float* __restrict__ Wv, const float* __restrict__ Wo,
                              __nv_bfloat16* __restrict__ wh, __nv_bfloat16* __restrict__ wl)
{
    const int z = blockIdx.y;
    const float* W = (z == 0) ? Wq : (z == 1) ? Wk : (z == 2) ? Wv : Wo;
    const size_t base = (size_t)z * DD_;
    const size_t idx = ((size_t)blockIdx.x * 256 + threadIdx.x) * 4;
    const float4 v = *(const float4*)(W + idx);
    const float vv[4] = {v.x, v.y, v.z, v.w};
    uint32_t h01, h23, l01, l23;
    split4(vv, h01, h23, l01, l23);
    *(uint2*)(wh + base + idx) = make_uint2(h01, h23);
    *(uint2*)(wl + base + idx) = make_uint2(l01, l23);
}

// ---------------- HMMA GEMM (split-bf16, 3-pass, cp.async) -------------------
// C = scale*(A @ W^T) (+res).  CTA 128x256, BK=32, 256 thr = 8 warps (2x4),
// warp tile 64x64 (crossbar-bound fix: 128 LDS per 192 HMMA per warp-iter).
// MODE 0: fp32 out + residual.  MODE 1: split-bf16 out (Ch, Cl).
#define GSTRIDE 20
#define AW_  2560                 // words per A plane (128*20)
#define BW_  5120                 // words per B plane (256*20)
#define STW_ (2*AW_ + 2*BW_)      // 15360 words per stage
#define GEMM_SMEM (2*STW_*4)      // 122880 bytes

template<int MODE>
__device__ __forceinline__ void mma_gemm_body(
    const __nv_bfloat16* __restrict__ Ah, const __nv_bfloat16* __restrict__ Al,
    const __nv_bfloat16* __restrict__ Bh, const __nv_bfloat16* __restrict__ Bl,
    float* __restrict__ Cf, const float* __restrict__ res,
    __nv_bfloat16* __restrict__ Ch, __nv_bfloat16* __restrict__ Cl, float scale)
{
    extern __shared__ uint32_t smw[];
    const uint32_t sbase = (uint32_t)__cvta_generic_to_shared(smw);

    const int tid  = threadIdx.x;
    const int warp = tid >> 5, lane = tid & 31;
    const int wm = warp >> 2, wn = warp & 3;        // 2x4 warp grid
    const int g  = lane >> 2, t = lane & 3;
    const int m0 = blockIdx.y * 128, n0 = blockIdx.x * 256;

    float acc[4][8][4];
    #pragma unroll
    for (int i = 0; i < 4; i++)
        #pragma unroll
        for (int j = 0; j < 8; j++)
            #pragma unroll
            for (int c = 0; c < 4; c++) acc[i][j][c] = 0.f;

    auto LOAD = [&](int k0, int st) {
        const uint32_t stw = (uint32_t)st * STW_;
        #pragma unroll
        for (int h = 0; h < 2; h++) {                  // A: 128 rows x 4 chunks
            const int idx = tid + h * 256;
            const int row = idx >> 2;
            const int w0  = (idx & 3) * 4;
            const size_t ga = (size_t)(m0 + row) * D_ + k0 + w0 * 2;
            const uint32_t d = sbase + (stw + (uint32_t)(row * GSTRIDE + w0)) * 4;
            CPA16(d,           Ah + ga);
            CPA16(d + AW_ * 4, Al + ga);
        }
        #pragma unroll
        for (int h = 0; h < 4; h++) {                  // B: 256 rows x 4 chunks
            const int idx = tid + h * 256;
            const int row = idx >> 2;
            const int w0  = (idx & 3) * 4;
            const size_t gb = (size_t)(n0 + row) * D_ + k0 + w0 * 2;
            const uint32_t d = sbase + (stw + 2*AW_ + (uint32_t)(row * GSTRIDE + w0)) * 4;
            CPA16(d,           Bh + gb);
            CPA16(d + BW_ * 4, Bl + gb);
        }
    };

    LOAD(0, 0);
    CPA_COMMIT();

    for (int it = 0; it < D_ / 32; it++) {
        const int cur = it & 1;
        if (it + 1 < D_ / 32) {
            LOAD((it + 1) * 32, cur ^ 1);
            CPA_COMMIT();
            CPA_WAIT1();
        } else {
            CPA_WAIT0();
        }
        __syncthreads();

        const uint32_t* sAh = smw + cur * STW_;
        const uint32_t* sAl = sAh + AW_;
        const uint32_t* sBh = sAl + AW_;
        const uint32_t* sBl = sBh + BW_;

        #pragma unroll
        for (int ks = 0; ks < 2; ks++) {
            const int w0 = ks * 8 + t;
            uint32_t ah[4][4], al[4][4];
            #pragma unroll
            for (int i = 0; i < 4; i++) {
                const int r = wm * 64 + i * 16 + g;
                ah[i][0] = sAh[r*GSTRIDE + w0];       ah[i][1] = sAh[(r+8)*GSTRIDE + w0];
                ah[i][2] = sAh[r*GSTRIDE + w0 + 4];   ah[i][3] = sAh[(r+8)*GSTRIDE + w0 + 4];
                al[i][0] = sAl[r*GSTRIDE + w0];       al[i][1] = sAl[(r+8)*GSTRIDE + w0];
                al[i][2] = sAl[r*GSTRIDE + w0 + 4];   al[i][3] = sAl[(r+8)*GSTRIDE + w0 + 4];
            }
            #pragma unroll
            for (int j = 0; j < 8; j++) {
                const int n = wn * 64 + j * 8 + g;
                const uint32_t bhf[2] = {sBh[n*GSTRIDE + w0], sBh[n*GSTRIDE + w0 + 4]};
                const uint32_t blf[2] = {sBl[n*GSTRIDE + w0], sBl[n*GSTRIDE + w0 + 4]};
                #pragma unroll
                for (int i = 0; i < 4; i++) {
                    mma16816(acc[i][j], ah[i], bhf);
                    mma16816(acc[i][j], al[i], bhf);
                    mma16816(acc[i][j], ah[i], blf);
                }
            }
        }
        __syncthreads();
    }

    #pragma unroll
    for (int i = 0; i < 4; i++) {
        const int r0 = m0 + wm * 64 + i * 16 + g;
        #pragma unroll
        for (int j = 0; j < 8; j++) {
            const int c = n0 + wn * 64 + j * 8 + 2 * t;
            const float x0 = acc[i][j][0] * scale, x1 = acc[i][j][1] * scale;
            const float x2 = acc[i][j][2] * scale, x3 = acc[i][j][3] * scale;
            if (MODE == 0) {
                const float2 r0v = *(const float2*)(res + (size_t)r0 * D_ + c);
                const float2 r1v = *(const float2*)(res + (size_t)(r0+8) * D_ + c);
                *(float2*)(Cf + (size_t)r0     * D_ + c) = make_float2(x0 + r0v.x, x1 + r0v.y);
                *(float2*)(Cf + (size_t)(r0+8) * D_ + c) = make_float2(x2 + r1v.x, x3 + r1v.y);
            } else {
                uint32_t hp, lp;
                split2pack(x0, x1, hp, lp);
                *(uint32_t*)(Ch + (size_t)r0 * D_ + c) = hp;
                *(uint32_t*)(Cl + (size_t)r0 * D_ + c) = lp;
                split2pack(x2, x3, hp, lp);
                *(uint32_t*)(Ch + (size_t)(r0+8) * D_ + c) = hp;
                *(uint32_t*)(Cl + (size_t)(r0+8) * D_ + c) = lp;
            }
        }
    }
}

__global__ __launch_bounds__(256, 1)
void qkv_kernel(const __nv_bfloat16* __restrict__ xnh, const __nv_bfloat16* __restrict__ xnl,
                const __nv_bfloat16* __restrict__ wh,  const __nv_bfloat16* __restrict__ wl,
                __nv_bfloat16* __restrict__ qh, __nv_bfloat16* __restrict__ ql,
                __nv_bfloat16* __restrict__ kh, __nv_bfloat16* __restrict__ kl,
                __nv_bfloat16* __restrict__ vh, __nv_bfloat16* __restrict__ vl)
{
    const int z = blockIdx.z;
    __nv_bfloat16 *Ch, *Cl;
    if (z == 0)      { Ch = qh; Cl = ql; }
    else if (z == 1) { Ch = kh; Cl = kl; }
    else             { Ch = vh; Cl = vl; }
    const float scale = (z == 0) ? 0.125f : 1.0f;
    mma_gemm_body<1>(xnh, xnl, wh + (size_t)z*DD_, wl + (size_t)z*DD_,
                     nullptr, nullptr, Ch, Cl, scale);
}

__global__ __launch_bounds__(256, 1)
void out_kernel(const __nv_bfloat16* __restrict__ yh, const __nv_bfloat16* __restrict__ yl,
                const __nv_bfloat16* __restrict__ wh, const __nv_bfloat16* __restrict__ wl,
                const float* __restrict__ x, float* __restrict__ out)
{
    mma_gemm_body<0>(yh, yl, wh + (size_t)3*DD_, wl + (size_t)3*DD_,
                     out, x, nullptr, nullptr, 1.0f);
}

// ---------------- HMMA flash attention (R13-proven) ---------------------------
// Grid (32, 16, 4), 128 threads = 4 warps; warp owns 16 Q rows (Q tile 64).
// Q fragments loaded directly from GMEM into registers (no Q smem) -> dynamic
// smem 65KB -> 3 CTAs/SM (12 warps). K/V double-buffered via cp.async.
#define ATTN_SMEM (2*32768 + 1024)

__global__ __launch_bounds__(128)
void attn_tc(const __nv_bfloat16* __restrict__ qh, const __nv_bfloat16* __restrict__ ql,
             const __nv_bfloat16* __restrict__ kh, const __nv_bfloat16* __restrict__ kl,
             const __nv_bfloat16* __restrict__ vh, const __nv_bfloat16* __restrict__ vl,
             const float* __restrict__ rel,
             __nv_bfloat16* __restrict__ yh, __nv_bfloat16* __restrict__ yl)
{
    extern __shared__ char dynsm[];
    __shared__ float rels[MAXREL + 1];
    const uint32_t sb = (sm_u32(dynsm) + 1023u) & ~1023u;

    const int qb = 31 - (int)blockIdx.x;     // heavy blocks first
    const int h  = blockIdx.y;
    const int b  = blockIdx.z;
    const int tid = threadIdx.x;
    const int warp = tid >> 5, lane = tid & 31;
    const int nit = qb + 1;
    const int qrow0 = b*T_ + qb*64;
    const int hoff = h * DH_;

    auto LDKV = [&](int kb, int st) {
        const uint32_t s0 = sb + st * 32768;
        const int krow0 = b*T_ + kb*64;
        #pragma unroll
        for (int t = 0; t < 4; t++) {
            const int idx = tid + t*128, r = idx >> 3, c = idx & 7;
            const uint32_t o = SMEM_SWZ(r*128 + c*16);
            const size_t gk = (size_t)(krow0 + r)*D_ + hoff + c*8;
            CPA16(s0 +         o, kh + gk);
            CPA16(s0 +  8192 + o, kl + gk);
            CPA16(s0 + 16384 + o, vh + gk);
            CPA16(s0 + 24576 + o, vl + gk);
        }
    };

    LDKV(0, 0); CPA_COMMIT();
    if (nit > 1) { LDKV(1, 1); CPA_COMMIT(); }
    for (int i = tid; i <= MAXREL; i += 128) rels[i] = rel[h*(MAXREL+1) + i];

    // ---- Q fragments direct from gmem (m16n8k16 A layout) ----
    const int g  = lane >> 2, t2 = (lane & 3) * 2;
    const int r0g = qrow0 + warp*16 + g;
    uint32_t qfh[4][4], qfl[4][4];
    #pragma unroll
    for (int c = 0; c < 4; c++) {
        const size_t b0 = (size_t)r0g       * D_ + hoff + c*16 + t2;
        const size_t b1 = (size_t)(r0g + 8) * D_ + hoff + c*16 + t2;
        qfh[c][0] = *(const uint32_t*)(qh + b0);
        qfh[c][1] = *(const uint32_t*)(qh + b1);
        qfh[c][2] = *(const uint32_t*)(qh + b0 + 8);
        qfh[c][3] = *(const uint32_t*)(qh + b1 + 8);
        qfl[c][0] = *(const uint32_t*)(ql + b0);
        qfl[c][1] = *(const uint32_t*)(ql + b1);
        qfl[c][2] = *(const uint32_t*)(ql + b0 + 8);
        qfl[c][3] = *(const uint32_t*)(ql + b1 + 8);
    }

    const int rkoff = (lane & 7) + ((lane >> 4) & 1) * 8;   // K rows (non-trans B)
    const int ckK   = (lane >> 3) & 1;
    const int rvoff = (lane & 7) + ((lane >> 3) & 1) * 8;   // V rows (trans B)
    const int cvK   = (lane >> 4) & 1;
    const uint32_t xorL = (uint32_t)(lane & 7) * 16;

    float m0 = -1e30f, m1 = -1e30f, l0 = 0.f, l1 = 0.f;
    float o[8][4];
    #pragma unroll
    for (int dt = 0; dt < 8; dt++)
        #pragma unroll
        for (int e = 0; e < 4; e++) o[dt][e] = 0.f;

    const int rq0 = qb*64 + warp*16 + g;                // global i of row0 (row1 = +8)

    for (int it = 0; it < nit; it++) {
        if (it + 1 < nit) CPA_WAIT1(); else CPA_WAIT0();
        __syncthreads();
        const uint32_t s0 = sb + (it & 1) * 32768;

        // -------- S = Q K^T (3-pass) --------
        float s[8][4];
        #pragma unroll
        for (int jt = 0; jt < 8; jt++)
            #pragma unroll
            for (int e = 0; e < 4; e++) s[jt][e] = 0.f;

        #pragma unroll
        for (int d8 = 0; d8 < 8; d8 += 2) {             // d0 = d8*8, k-step 16
            const uint32_t* aqhf = qfh[d8 >> 1];
            const uint32_t* aqlf = qfl[d8 >> 1];
            #pragma unroll
            for (int jp = 0; jp < 4; jp++) {
                const uint32_t ka = s0 + (uint32_t)(jp*16 + rkoff)*128
                                  + ((uint32_t)((d8 + ckK) * 16) ^ xorL);
                uint32_t bh4[4], bl4[4];
                LDSM4(bh4, ka);
                LDSM4(bl4, ka + 8192);
                mma16816(s[2*jp],   aqhf, bh4);
                mma16816(s[2*jp],   aqlf, bh4);
                mma16816(s[2*jp],   aqhf, bl4);
                mma16816(s[2*jp+1], aqhf, bh4 + 2);
                mma16816(s[2*jp+1], aqlf, bh4 + 2);
                mma16816(s[2*jp+1], aqhf, bl4 + 2);
            }
        }

        // -------- bias + causal mask --------
        const int jbase = it*64 + 2*(lane & 3);
        #pragma unroll
        for (int jt = 0; jt < 8; jt++) {
            #pragma unroll
            for (int e = 0; e < 2; e++) {
                const int jc = jbase + jt*8 + e;
                const int d0v = rq0 - jc;
                const int d1v = d0v + 8;
                s[jt][e]     = (d0v < 0) ? -1e30f : s[jt][e]     + rels[d0v > MAXREL ? MAXREL : d0v];
                s[jt][2 + e] = (d1v < 0) ? -1e30f : s[jt][2 + e] + rels[d1v > MAXREL ? MAXREL : d1v];
            }
        }

        // -------- online softmax --------
        float mx0 = -1e30f, mx1 = -1e30f;
        #pragma unroll
        for (int jt = 0; jt < 8; jt++) {
            mx0 = fmaxf(mx0, fmaxf(s[jt][0], s[jt][1]));
            mx1 = fmaxf(mx1, fmaxf(s[jt][2], s[jt][3]));
        }
        mx0 = fmaxf(mx0, __shfl_xor_sync(0xffffffffu, mx0, 1));
        mx0 = fmaxf(mx0, __shfl_xor_sync(0xffffffffu, mx0, 2));
        mx1 = fmaxf(mx1, __shfl_xor_sync(0xffffffffu, mx1, 1));
        mx1 = fmaxf(mx1, __shfl_xor_sync(0xffffffffu, mx1, 2));
        const float mn0 = fmaxf(m0, mx0), mn1 = fmaxf(m1, mx1);
        const float a0 = __expf(m0 - mn0), a1 = __expf(m1 - mn1);
        m0 = mn0; m1 = mn1;
        float rs0 = 0.f, rs1 = 0.f;
        #pragma unroll
        for (int jt = 0; jt < 8; jt++) {
            #pragma unroll
            for (int e = 0; e < 2; e++) {
                s[jt][e]     = __expf(s[jt][e]     - mn0);  rs0 += s[jt][e];
                s[jt][2 + e] = __expf(s[jt][2 + e] - mn1);  rs1 += s[jt][2 + e];
            }
        }
        rs0 += __shfl_xor_sync(0xffffffffu, rs0, 1);
        rs0 += __shfl_xor_sync(0xffffffffu, rs0, 2);
        rs1 += __shfl_xor_sync(0xffffffffu, rs1, 1);
        rs1 += __shfl_xor_sync(0xffffffffu, rs1, 2);
        l0 = l0 * a0 + rs0;
        l1 = l1 * a1 + rs1;
        #pragma unroll
        for (int dt = 0; dt < 8; dt++) {
            o[dt][0] *= a0; o[dt][1] *= a0;
            o[dt][2] *= a1; o[dt][3] *= a1;
        }

        // -------- O += P V (3-pass) --------
        #pragma unroll
        for (int jp = 0; jp < 4; jp++) {
            uint32_t ph[4], pl[4];
            split2pack(s[2*jp][0],   s[2*jp][1],   ph[0], pl[0]);
            split2pack(s[2*jp][2],   s[2*jp][3],   ph[1], pl[1]);
            split2pack(s[2*jp+1][0], s[2*jp+1][1], ph[2], pl[2]);
            split2pack(s[2*jp+1][2], s[2*jp+1][3], ph[3], pl[3]);
            #pragma unroll
            for (int dp = 0; dp < 4; dp++) {
                const uint32_t va = s0 + 16384 + (uint32_t)(jp*16 + rvoff)*128
                                  + ((uint32_t)((dp*2 + cvK) * 16) ^ xorL);
                uint32_t wh4[4], wl4[4];
                LDSM4T(wh4, va);
                LDSM4T(wl4, va + 8192);
                mma16816(o[2*dp],   ph, wh4);
                mma16816(o[2*dp],   pl, wh4);
                mma16816(o[2*dp],   ph, wl4);
                mma16816(o[2*dp+1], ph, wh4 + 2);
                mma16816(o[2*dp+1], pl, wh4 + 2);
                mma16816(o[2*dp+1], ph, wl4 + 2);
            }
        }

        __syncthreads();
        if (it + 2 < nit) { LDKV(it + 2, it & 1); CPA_COMMIT(); }
    }

    // -------- epilogue: normalize, split, store --------
    const float i0 = 1.0f / l0, i1 = 1.0f / l1;
    const int gr0 = qrow0 + warp*16 + g;
    const int colb = hoff + 2*(lane & 3);
    #pragma unroll
    for (int dt = 0; dt < 8; dt++) {
        const int col = colb + dt*8;
        uint32_t hp, lp;
        split2pack(o[dt][0] * i0, o[dt][1] * i0, hp, lp);
        *(uint32_t*)(yh + (size_t)gr0 * D_ + col) = hp;
        *(uint32_t*)(yl + (size_t)gr0 * D_ + col) = lp;
        split2pack(o[dt][2] * i1, o[dt][3] * i1, hp, lp);
        *(uint32_t*)(yh + (size_t)(gr0 + 8) * D_ + col) = hp;
        *(uint32_t*)(yl + (size_t)(gr0 + 8) * D_ + col) = lp;
    }
}

extern "C" void kernel_launch(void* const* d_in, const int* in_sizes, int n_in,
                              void* d_out, int out_size)
{
    const float* x     = (const float*)d_in[0];
    const float* Wq    = (const float*)d_in[1];
    const float* Wk    = (const float*)d_in[2];
    const float* Wv    = (const float*)d_in[3];
    const float* Wo    = (const float*)d_in[4];
    const float* rel   = (const float*)d_in[5];
    const float* gamma = (const float*)d_in[6];
    const float* beta  = (const float*)d_in[7];
    float* out = (float*)d_out;

    __nv_bfloat16 *p_xnh, *p_xnl, *p_wh, *p_wl, *p_yh, *p_yl;
    __nv_bfloat16 *p_qh, *p_ql, *p_kh, *p_kl, *p_vh, *p_vl;
    cudaGetSymbolAddress((void**)&p_xnh, g_xnh);
    cudaGetSymbolAddress((void**)&p_xnl, g_xnl);
    cudaGetSymbolAddress((void**)&p_wh,  g_wh);
    cudaGetSymbolAddress((void**)&p_wl,  g_wl);
    cudaGetSymbolAddress((void**)&p_yh,  g_yh);
    cudaGetSymbolAddress((void**)&p_yl,  g_yl);
    cudaGetSymbolAddress((void**)&p_qh,  g_qh);
    cudaGetSymbolAddress((void**)&p_ql,  g_ql);
    cudaGetSymbolAddress((void**)&p_kh,  g_kh);
    cudaGetSymbolAddress((void**)&p_kl,  g_kl);
    cudaGetSymbolAddress((void**)&p_vh,  g_vh);
    cudaGetSymbolAddress((void**)&p_vl,  g_vl);

    cudaFuncSetAttribute(qkv_kernel, cudaFuncAttributeMaxDynamicSharedMemorySize, GEMM_SMEM);
    cudaFuncSetAttribute(out_kernel, cudaFuncAttributeMaxDynamicSharedMemorySize, GEMM_SMEM);
    cudaFuncSetAttribute(attn_tc,    cudaFuncAttributeMaxDynamicSharedMemorySize, ATTN_SMEM);

    ln_kernel<<<M_, 256>>>(x, gamma, beta, p_xnh, p_xnl);
    wsplit_kernel<<<dim3(DD_/(256*4), 4), 256>>>(Wq, Wk, Wv, Wo, p_wh, p_wl);
    qkv_kernel<<<dim3(D_/256, M_/128, 3), 256, GEMM_SMEM>>>(p_xnh, p_xnl, p_wh, p_wl,
                                                            p_qh, p_ql, p_kh, p_kl, p_vh, p_vl);
    attn_tc<<<dim3(T_/64, H_, B_), 128, ATTN_SMEM>>>(p_qh, p_ql, p_kh, p_kl, p_vh, p_vl,
                                                     rel, p_yh, p_yl);
    out_kernel<<<dim3(D_/256, M_/128), 256, GEMM_SMEM>>>(p_yh, p_yl, p_wh, p_wl, x, out);
}

// round 17
// speedup vs baseline: 1.0701x; 1.0701x over previous
#include <cuda_runtime.h>
#include <cuda_bf16.h>
#include <math.h>
#include <stdint.h>

#define B_  4
#define T_  2048
#define D_  1024
#define H_  16
#define DH_ 64
#define M_  (B_*T_)      // 8192 rows
#define MAXREL 128
#define DD_ (D_*D_)

// ---------------- scratch (device globals; no allocs allowed) ----------------
__device__ __nv_bfloat16 g_xnh[M_*D_], g_xnl[M_*D_];     // LN output, split bf16
__device__ __nv_bfloat16 g_wh[4*DD_],  g_wl[4*DD_];      // Wq,Wk,Wv,Wo split
__device__ __nv_bfloat16 g_yh[M_*D_],  g_yl[M_*D_];      // attention output, split
__device__ __nv_bfloat16 g_qh[M_*D_],  g_ql[M_*D_];
__device__ __nv_bfloat16 g_kh[M_*D_],  g_kl[M_*D_];
__device__ __nv_bfloat16 g_vh[M_*D_],  g_vl[M_*D_];

// ---------------- helpers ----------------
__device__ __forceinline__ uint32_t bf2_pack(__nv_bfloat16 a, __nv_bfloat16 b)
{
    __nv_bfloat162 p = __halves2bfloat162(a, b);   // a -> low 16 bits
    return *reinterpret_cast<uint32_t*>(&p);
}

__device__ __forceinline__ void split2pack(float a, float b, uint32_t& hp, uint32_t& lp)
{
    __nv_bfloat16 ah = __float2bfloat16_rn(a), bh = __float2bfloat16_rn(b);
    __nv_bfloat16 al = __float2bfloat16_rn(a - __bfloat162float(ah));
    __nv_bfloat16 bl = __float2bfloat16_rn(b - __bfloat162float(bh));
    hp = bf2_pack(ah, bh);
    lp = bf2_pack(al, bl);
}

__device__ __forceinline__ void split4(const float* v, uint32_t& h01, uint32_t& h23,
                                       uint32_t& l01, uint32_t& l23)
{
    split2pack(v[0], v[1], h01, l01);
    split2pack(v[2], v[3], h23, l23);
}

__device__ __forceinline__ uint32_t sm_u32(const void* p)
{
    uint32_t a;
    asm("{ .reg .u64 t; cvta.to.shared.u64 t, %1; cvt.u32.u64 %0, t; }" : "=r"(a) : "l"(p));
    return a;
}

__device__ __forceinline__ void mma16816(float* d, const uint32_t* a, const uint32_t* b)
{
    asm volatile(
        "mma.sync.aligned.m16n8k16.row.col.f32.bf16.bf16.f32 "
        "{%0,%1,%2,%3}, {%4,%5,%6,%7}, {%8,%9}, {%0,%1,%2,%3};\n"
        : "+f"(d[0]), "+f"(d[1]), "+f"(d[2]), "+f"(d[3])
        : "r"(a[0]), "r"(a[1]), "r"(a[2]), "r"(a[3]), "r"(b[0]), "r"(b[1]));
}

#define CPA16(dst, src) asm volatile("cp.async.cg.shared.global [%0], [%1], 16;\n" :: "r"(dst), "l"(src))
#define CPA_COMMIT()    asm volatile("cp.async.commit_group;\n" ::)
#define CPA_WAIT1()     asm volatile("cp.async.wait_group 1;\n" ::)
#define CPA_WAIT0()     asm volatile("cp.async.wait_group 0;\n" ::)

#define LDSM4(R, a) asm volatile( \
    "ldmatrix.sync.aligned.m8n8.x4.shared.b16 {%0,%1,%2,%3}, [%4];" \
    : "=r"((R)[0]), "=r"((R)[1]), "=r"((R)[2]), "=r"((R)[3]) : "r"(a))
#define LDSM4T(R, a) asm volatile( \
    "ldmatrix.sync.aligned.m8n8.x4.trans.shared.b16 {%0,%1,%2,%3}, [%4];" \
    : "=r"((R)[0]), "=r"((R)[1]), "=r"((R)[2]), "=r"((R)[3]) : "r"(a))

#define SMEM_SWZ(o) ((uint32_t)(o) ^ ((((uint32_t)(o)) >> 3) & 0x70u))

// ---------------- LayerNorm: one block per row, writes split bf16 ------------
__global__ void ln_kernel(const float* __restrict__ x, const float* __restrict__ gamma,
                          const float* __restrict__ beta,
                          __nv_bfloat16* __restrict__ xnh, __nv_bfloat16* __restrict__ xnl)
{
    const int row = blockIdx.x;
    const int tid = threadIdx.x;
    const float4 v = *(const float4*)(x + (size_t)row*D_ + tid*4);
    float s  = v.x + v.y + v.z + v.w;
    float ss = v.x*v.x + v.y*v.y + v.z*v.z + v.w*v.w;
    #pragma unroll
    for (int off = 16; off; off >>= 1) {
        s  += __shfl_xor_sync(0xffffffffu, s,  off);
        ss += __shfl_xor_sync(0xffffffffu, ss, off);
    }
    __shared__ float sh_s[8], sh_ss[8];
    const int w = tid >> 5;
    if ((tid & 31) == 0) { sh_s[w] = s; sh_ss[w] = ss; }
    __syncthreads();
    float ts = 0.f, tss = 0.f;
    #pragma unroll
    for (int i = 0; i < 8; i++) { ts += sh_s[i]; tss += sh_ss[i]; }
    const float mu   = ts * (1.0f / D_);
    const float var  = tss * (1.0f / D_) - mu * mu;
    const float rstd = rsqrtf(var + 1e-5f);
    const float4 gv = *(const float4*)(gamma + tid*4);
    const float4 bv = *(const float4*)(beta  + tid*4);
    float o[4];
    o[0] = (v.x - mu) * rstd * gv.x + bv.x;
    o[1] = (v.y - mu) * rstd * gv.y + bv.y;
    o[2] = (v.z - mu) * rstd * gv.z + bv.z;
    o[3] = (v.w - mu) * rstd * gv.w + bv.w;
    uint32_t h01, h23, l01, l23;
    split4(o, h01, h23, l01, l23);
    *(uint2*)(xnh + (size_t)row*D_ + tid*4) = make_uint2(h01, h23);
    *(uint2*)(xnl + (size_t)row*D_ + tid*4) = make_uint2(l01, l23);
}

// ---------------- Weight split ----------------
__global__ void wsplit_kernel(const float* __restrict__ Wq, const float* __restrict__ Wk,
                              const float* __restrict__ Wv, const float* __restrict__ Wo,
                              __nv_bfloat16* __restrict__ wh, __nv_bfloat16* __restrict__ wl)
{
    const int z = blockIdx.y;
    const float* W = (z == 0) ? Wq : (z == 1) ? Wk : (z == 2) ? Wv : Wo;
    const size_t base = (size_t)z * DD_;
    const size_t idx = ((size_t)blockIdx.x * 256 + threadIdx.x) * 4;
    const float4 v = *(const float4*)(W + idx);
    const float vv[4] = {v.x, v.y, v.z, v.w};
    uint32_t h01, h23, l01, l23;
    split4(vv, h01, h23, l01, l23);
    *(uint2*)(wh + base + idx) = make_uint2(h01, h23);
    *(uint2*)(wl + base + idx) = make_uint2(l01, l23);
}

// ---------------- HMMA GEMM (split-bf16, 3-pass, cp.async) -------------------
// C = scale*(A @ W^T) (+res).  CTA 128x128, BK=32, 256 thr = 8 warps (4x2).
// MODE 0: fp32 out + residual.  MODE 1: split-bf16 out (Ch, Cl).
// (R8-proven body, scalar LDS fragments.)
#define GSTRIDE 20
#define ARR_W   (128*GSTRIDE)
#define GEMM_SMEM (2*4*ARR_W*4)

template<int MODE>
__device__ __forceinline__ void mma_gemm_body(
    const __nv_bfloat16* __restrict__ Ah, const __nv_bfloat16* __restrict__ Al,
    const __nv_bfloat16* __restrict__ Bh, const __nv_bfloat16* __restrict__ Bl,
    float* __restrict__ Cf, const float* __restrict__ res,
    __nv_bfloat16* __restrict__ Ch, __nv_bfloat16* __restrict__ Cl, float scale)
{
    extern __shared__ uint32_t smw[];
    const uint32_t sbase = (uint32_t)__cvta_generic_to_shared(smw);

    const int tid  = threadIdx.x;
    const int warp = tid >> 5, lane = tid & 31;
    const int wm = warp >> 1, wn = warp & 1;
    const int g  = lane >> 2, t = lane & 3;
    const int m0 = blockIdx.y * 128, n0 = blockIdx.x * 128;

    float acc[2][8][4];
    #pragma unroll
    for (int i = 0; i < 2; i++)
        #pragma unroll
        for (int j = 0; j < 8; j++)
            #pragma unroll
            for (int c = 0; c < 4; c++) acc[i][j][c] = 0.f;

    auto LOAD = [&](int k0, int st) {
        #pragma unroll
        for (int half = 0; half < 2; half++) {
            const int c   = tid + half * 256;
            const int row = c >> 2;
            const int w0  = (c & 3) * 4;
            const size_t ga = (size_t)(m0 + row) * D_ + k0 + w0 * 2;
            const size_t gb = (size_t)(n0 + row) * D_ + k0 + w0 * 2;
            const uint32_t dbase = sbase + (uint32_t)((st * 4 * ARR_W) + row * GSTRIDE + w0) * 4;
            CPA16(dbase + 0 * ARR_W * 4, Ah + ga);
            CPA16(dbase + 1 * ARR_W * 4, Al + ga);
            CPA16(dbase + 2 * ARR_W * 4, Bh + gb);
            CPA16(dbase + 3 * ARR_W * 4, Bl + gb);
        }
    };

    LOAD(0, 0);
    CPA_COMMIT();

    for (int it = 0; it < D_ / 32; it++) {
        const int cur = it & 1;
        if (it + 1 < D_ / 32) {
            LOAD((it + 1) * 32, cur ^ 1);
            CPA_COMMIT();
            CPA_WAIT1();
        } else {
            CPA_WAIT0();
        }
        __syncthreads();

        const uint32_t* sAh = smw + cur * 4 * ARR_W;
        const uint32_t* sAl = sAh + ARR_W;
        const uint32_t* sBh = sAl + ARR_W;
        const uint32_t* sBl = sBh + ARR_W;

        #pragma unroll
        for (int ks = 0; ks < 2; ks++) {
            const int w0 = ks * 8 + t;
            uint32_t ah[2][4], al[2][4];
            #pragma unroll
            for (int i = 0; i < 2; i++) {
                const int r = wm * 32 + i * 16 + g;
                ah[i][0] = sAh[r*GSTRIDE + w0];       ah[i][1] = sAh[(r+8)*GSTRIDE + w0];
                ah[i][2] = sAh[r*GSTRIDE + w0 + 4];   ah[i][3] = sAh[(r+8)*GSTRIDE + w0 + 4];
                al[i][0] = sAl[r*GSTRIDE + w0];       al[i][1] = sAl[(r+8)*GSTRIDE + w0];
                al[i][2] = sAl[r*GSTRIDE + w0 + 4];   al[i][3] = sAl[(r+8)*GSTRIDE + w0 + 4];
            }
            #pragma unroll
            for (int j = 0; j < 8; j++) {
                const int n = wn * 64 + j * 8 + g;
                const uint32_t bhf[2] = {sBh[n*GSTRIDE + w0], sBh[n*GSTRIDE + w0 + 4]};
                const uint32_t blf[2] = {sBl[n*GSTRIDE + w0], sBl[n*GSTRIDE + w0 + 4]};
                #pragma unroll
                for (int i = 0; i < 2; i++) {
                    mma16816(acc[i][j], ah[i], bhf);
                    mma16816(acc[i][j], al[i], bhf);
                    mma16816(acc[i][j], ah[i], blf);
                }
            }
        }
        __syncthreads();
    }

    #pragma unroll
    for (int i = 0; i < 2; i++) {
        const int r0 = m0 + wm * 32 + i * 16 + g;
        #pragma unroll
        for (int j = 0; j < 8; j++) {
            const int c = n0 + wn * 64 + j * 8 + 2 * t;
            const float x0 = acc[i][j][0] * scale, x1 = acc[i][j][1] * scale;
            const float x2 = acc[i][j][2] * scale, x3 = acc[i][j][3] * scale;
            if (MODE == 0) {
                const float2 r0v = *(const float2*)(res + (size_t)r0 * D_ + c);
                const float2 r1v = *(const float2*)(res + (size_t)(r0+8) * D_ + c);
                *(float2*)(Cf + (size_t)r0     * D_ + c) = make_float2(x0 + r0v.x, x1 + r0v.y);
                *(float2*)(Cf + (size_t)(r0+8) * D_ + c) = make_float2(x2 + r1v.x, x3 + r1v.y);
            } else {
                uint32_t hp, lp;
                split2pack(x0, x1, hp, lp);
                *(uint32_t*)(Ch + (size_t)r0 * D_ + c) = hp;
                *(uint32_t*)(Cl + (size_t)r0 * D_ + c) = lp;
                split2pack(x2, x3, hp, lp);
                *(uint32_t*)(Ch + (size_t)(r0+8) * D_ + c) = hp;
                *(uint32_t*)(Cl + (size_t)(r0+8) * D_ + c) = lp;
            }
        }
    }
}

__global__ __launch_bounds__(256, 2)
void qkv_kernel(const __nv_bfloat16* __restrict__ xnh, const __nv_bfloat16* __restrict__ xnl,
                const __nv_bfloat16* __restrict__ wh,  const __nv_bfloat16* __restrict__ wl,
                __nv_bfloat16* __restrict__ qh, __nv_bfloat16* __restrict__ ql,
                __nv_bfloat16* __restrict__ kh, __nv_bfloat16* __restrict__ kl,
                __nv_bfloat16* __restrict__ vh, __nv_bfloat16* __restrict__ vl)
{
    const int z = blockIdx.z;
    __nv_bfloat16 *Ch, *Cl;
    if (z == 0)      { Ch = qh; Cl = ql; }
    else if (z == 1) { Ch = kh; Cl = kl; }
    else             { Ch = vh; Cl = vl; }
    const float scale = (z == 0) ? 0.125f : 1.0f;
    mma_gemm_body<1>(xnh, xnl, wh + (size_t)z*DD_, wl + (size_t)z*DD_,
                     nullptr, nullptr, Ch, Cl, scale);
}

__global__ __launch_bounds__(256, 2)
void out_kernel(const __nv_bfloat16* __restrict__ yh, const __nv_bfloat16* __restrict__ yl,
                const __nv_bfloat16* __restrict__ wh, const __nv_bfloat16* __restrict__ wl,
                const float* __restrict__ x, float* __restrict__ out)
{
    mma_gemm_body<0>(yh, yl, wh + (size_t)3*DD_, wl + (size_t)3*DD_,
                     out, x, nullptr, nullptr, 1.0f);
}

// ---------------- HMMA flash attention ---------------------------------------
// Grid (32, 16, 4), 128 threads = 4 warps; warp owns 16 Q rows (Q tile 64).
// Q fragments direct from GMEM (no Q smem) -> 3 CTAs/SM. K/V double-buffered.
// Far-tile fast path: dist >= MAXREL for whole warp tile -> constant bias,
// no causal check, no rels[] lookups (bit-identical math).
#define ATTN_SMEM (2*32768 + 1024)

__global__ __launch_bounds__(128)
void attn_tc(const __nv_bfloat16* __restrict__ qh, const __nv_bfloat16* __restrict__ ql,
             const __nv_bfloat16* __restrict__ kh, const __nv_bfloat16* __restrict__ kl,
             const __nv_bfloat16* __restrict__ vh, const __nv_bfloat16* __restrict__ vl,
             const float* __restrict__ rel,
             __nv_bfloat16* __restrict__ yh, __nv_bfloat16* __restrict__ yl)
{
    extern __shared__ char dynsm[];
    __shared__ float rels[MAXREL + 1];
    const uint32_t sb = (sm_u32(dynsm) + 1023u) & ~1023u;

    const int qb = 31 - (int)blockIdx.x;     // heavy blocks first
    const int h  = blockIdx.y;
    const int b  = blockIdx.z;
    const int tid = threadIdx.x;
    const int warp = tid >> 5, lane = tid & 31;
    const int nit = qb + 1;
    const int qrow0 = b*T_ + qb*64;
    const int hoff = h * DH_;

    const float bias_c = __ldg(rel + h*(MAXREL+1) + MAXREL);   // clamp value

    auto LDKV = [&](int kb, int st) {
        const uint32_t s0 = sb + st * 32768;
        const int krow0 = b*T_ + kb*64;
        #pragma unroll
        for (int t = 0; t < 4; t++) {
            const int idx = tid + t*128, r = idx >> 3, c = idx & 7;
            const uint32_t o = SMEM_SWZ(r*128 + c*16);
            const size_t gk = (size_t)(krow0 + r)*D_ + hoff + c*8;
            CPA16(s0 +         o, kh + gk);
            CPA16(s0 +  8192 + o, kl + gk);
            CPA16(s0 + 16384 + o, vh + gk);
            CPA16(s0 + 24576 + o, vl + gk);
        }
    };

    LDKV(0, 0); CPA_COMMIT();
    if (nit > 1) { LDKV(1, 1); CPA_COMMIT(); }
    for (int i = tid; i <= MAXREL; i += 128) rels[i] = rel[h*(MAXREL+1) + i];

    // ---- Q fragments direct from gmem (m16n8k16 A layout) ----
    const int g  = lane >> 2, t2 = (lane & 3) * 2;
    const int r0g = qrow0 + warp*16 + g;
    uint32_t qfh[4][4], qfl[4][4];
    #pragma unroll
    for (int c = 0; c < 4; c++) {
        const size_t b0 = (size_t)r0g       * D_ + hoff + c*16 + t2;
        const size_t b1 = (size_t)(r0g + 8) * D_ + hoff + c*16 + t2;
        qfh[c][0] = *(const uint32_t*)(qh + b0);
        qfh[c][1] = *(const uint32_t*)(qh + b1);
        qfh[c][2] = *(const uint32_t*)(qh + b0 + 8);
        qfh[c][3] = *(const uint32_t*)(qh + b1 + 8);
        qfl[c][0] = *(const uint32_t*)(ql + b0);
        qfl[c][1] = *(const uint32_t*)(ql + b1);
        qfl[c][2] = *(const uint32_t*)(ql + b0 + 8);
        qfl[c][3] = *(const uint32_t*)(ql + b1 + 8);
    }

    const int rkoff = (lane & 7) + ((lane >> 4) & 1) * 8;   // K rows (non-trans B)
    const int ckK   = (lane >> 3) & 1;
    const int rvoff = (lane & 7) + ((lane >> 3) & 1) * 8;   // V rows (trans B)
    const int cvK   = (lane >> 4) & 1;
    const uint32_t xorL = (uint32_t)(lane & 7) * 16;

    float m0 = -1e30f, m1 = -1e30f, l0 = 0.f, l1 = 0.f;
    float o[8][4];
    #pragma unroll
    for (int dt = 0; dt < 8; dt++)
        #pragma unroll
        for (int e = 0; e < 4; e++) o[dt][e] = 0.f;

    const int rq0 = qb*64 + warp*16 + g;                // global i of row0 (row1 = +8)
    const int wrow0 = qb*64 + warp*16;                  // warp's smallest i

    for (int it = 0; it < nit; it++) {
        if (it + 1 < nit) CPA_WAIT1(); else CPA_WAIT0();
        __syncthreads();
        const uint32_t s0 = sb + (it & 1) * 32768;

        // -------- S = Q K^T (3-pass) --------
        float s[8][4];
        #pragma unroll
        for (int jt = 0; jt < 8; jt++)
            #pragma unroll
            for (int e = 0; e < 4; e++) s[jt][e] = 0.f;

        #pragma unroll
        for (int d8 = 0; d8 < 8; d8 += 2) {             // d0 = d8*8, k-step 16
            const uint32_t* aqhf = qfh[d8 >> 1];
            const uint32_t* aqlf = qfl[d8 >> 1];
            #pragma unroll
            for (int jp = 0; jp < 4; jp++) {
                const uint32_t ka = s0 + (uint32_t)(jp*16 + rkoff)*128
                                  + ((uint32_t)((d8 + ckK) * 16) ^ xorL);
                uint32_t bh4[4], bl4[4];
                LDSM4(bh4, ka);
                LDSM4(bl4, ka + 8192);
                mma16816(s[2*jp],   aqhf, bh4);
                mma16816(s[2*jp],   aqlf, bh4);
                mma16816(s[2*jp],   aqhf, bl4);
                mma16816(s[2*jp+1], aqhf, bh4 + 2);
                mma16816(s[2*jp+1], aqlf, bh4 + 2);
                mma16816(s[2*jp+1], aqhf, bl4 + 2);
            }
        }

        // -------- bias + causal mask --------
        // Fast path: whole warp tile has dist >= MAXREL -> constant bias, no mask.
        if (wrow0 - (it*64 + 63) >= MAXREL) {
            #pragma unroll
            for (int jt = 0; jt < 8; jt++) {
                s[jt][0] += bias_c; s[jt][1] += bias_c;
                s[jt][2] += bias_c; s[jt][3] += bias_c;
            }
        } else {
            const int jbase = it*64 + 2*(lane & 3);
            #pragma unroll
            for (int jt = 0; jt < 8; jt++) {
                #pragma unroll
                for (int e = 0; e < 2; e++) {
                    const int jc = jbase + jt*8 + e;
                    const int d0v = rq0 - jc;
                    const int d1v = d0v + 8;
                    s[jt][e]     = (d0v < 0) ? -1e30f : s[jt][e]     + rels[d0v > MAXREL ? MAXREL : d0v];
                    s[jt][2 + e] = (d1v < 0) ? -1e30f : s[jt][2 + e] + rels[d1v > MAXREL ? MAXREL : d1v];
                }
            }
        }

        // -------- online softmax --------
        float mx0 = -1e30f, mx1 = -1e30f;
        #pragma unroll
        for (int jt = 0; jt < 8; jt++) {
            mx0 = fmaxf(mx0, fmaxf(s[jt][0], s[jt][1]));
            mx1 = fmaxf(mx1, fmaxf(s[jt][2], s[jt][3]));
        }
        mx0 = fmaxf(mx0, __shfl_xor_sync(0xffffffffu, mx0, 1));
        mx0 = fmaxf(mx0, __shfl_xor_sync(0xffffffffu, mx0, 2));
        mx1 = fmaxf(mx1, __shfl_xor_sync(0xffffffffu, mx1, 1));
        mx1 = fmaxf(mx1, __shfl_xor_sync(0xffffffffu, mx1, 2));
        const float mn0 = fmaxf(m0, mx0), mn1 = fmaxf(m1, mx1);
        const float a0 = __expf(m0 - mn0), a1 = __expf(m1 - mn1);
        m0 = mn0; m1 = mn1;
        float rs0 = 0.f, rs1 = 0.f;
        #pragma unroll
        for (int jt = 0; jt < 8; jt++) {
            #pragma unroll
            for (int e = 0; e < 2; e++) {
                s[jt][e]     = __expf(s[jt][e]     - mn0);  rs0 += s[jt][e];
                s[jt][2 + e] = __expf(s[jt][2 + e] - mn1);  rs1 += s[jt][2 + e];
            }
        }
        rs0 += __shfl_xor_sync(0xffffffffu, rs0, 1);
        rs0 += __shfl_xor_sync(0xffffffffu, rs0, 2);
        rs1 += __shfl_xor_sync(0xffffffffu, rs1, 1);
        rs1 += __shfl_xor_sync(0xffffffffu, rs1, 2);
        l0 = l0 * a0 + rs0;
        l1 = l1 * a1 + rs1;
        #pragma unroll
        for (int dt = 0; dt < 8; dt++) {
            o[dt][0] *= a0; o[dt][1] *= a0;
            o[dt][2] *= a1; o[dt][3] *= a1;
        }

        // -------- O += P V (3-pass) --------
        #pragma unroll
        for (int jp = 0; jp < 4; jp++) {
            uint32_t ph[4], pl[4];
            split2pack(s[2*jp][0],   s[2*jp][1],   ph[0], pl[0]);
            split2pack(s[2*jp][2],   s[2*jp][3],   ph[1], pl[1]);
            split2pack(s[2*jp+1][0], s[2*jp+1][1], ph[2], pl[2]);
            split2pack(s[2*jp+1][2], s[2*jp+1][3], ph[3], pl[3]);
            #pragma unroll
            for (int dp = 0; dp < 4; dp++) {
                const uint32_t va = s0 + 16384 + (uint32_t)(jp*16 + rvoff)*128
                                  + ((uint32_t)((dp*2 + cvK) * 16) ^ xorL);
                uint32_t wh4[4], wl4[4];
                LDSM4T(wh4, va);
                LDSM4T(wl4, va + 8192);
                mma16816(o[2*dp],   ph, wh4);
                mma16816(o[2*dp],   pl, wh4);
                mma16816(o[2*dp],   ph, wl4);
                mma16816(o[2*dp+1], ph, wh4 + 2);
                mma16816(o[2*dp+1], pl, wh4 + 2);
                mma16816(o[2*dp+1], ph, wl4 + 2);
            }
        }

        __syncthreads();
        if (it + 2 < nit) { LDKV(it + 2, it & 1); CPA_COMMIT(); }
    }

    // -------- epilogue: normalize, split, store --------
    const float i0 = 1.0f / l0, i1 = 1.0f / l1;
    const int gr0 = qrow0 + warp*16 + g;
    const int colb = hoff + 2*(lane & 3);
    #pragma unroll
    for (int dt = 0; dt < 8; dt++) {
        const int col = colb + dt*8;
        uint32_t hp, lp;
        split2pack(o[dt][0] * i0, o[dt][1] * i0, hp, lp);
        *(uint32_t*)(yh + (size_t)gr0 * D_ + col) = hp;
        *(uint32_t*)(yl + (size_t)gr0 * D_ + col) = lp;
        split2pack(o[dt][2] * i1, o[dt][3] * i1, hp, lp);
        *(uint32_t*)(yh + (size_t)(gr0 + 8) * D_ + col) = hp;
        *(uint32_t*)(yl + (size_t)(gr0 + 8) * D_ + col) = lp;
    }
}

extern "C" void kernel_launch(void* const* d_in, const int* in_sizes, int n_in,
                              void* d_out, int out_size)
{
    const float* x     = (const float*)d_in[0];
    const float* Wq    = (const float*)d_in[1];
    const float* Wk    = (const float*)d_in[2];
    const float* Wv    = (const float*)d_in[3];
    const float* Wo    = (const float*)d_in[4];
    const float* rel   = (const float*)d_in[5];
    const float* gamma = (const float*)d_in[6];
    const float* beta  = (const float*)d_in[7];
    float* out = (float*)d_out;

    __nv_bfloat16 *p_xnh, *p_xnl, *p_wh, *p_wl, *p_yh, *p_yl;
    __nv_bfloat16 *p_qh, *p_ql, *p_kh, *p_kl, *p_vh, *p_vl;
    cudaGetSymbolAddress((void**)&p_xnh, g_xnh);
    cudaGetSymbolAddress((void**)&p_xnl, g_xnl);
    cudaGetSymbolAddress((void**)&p_wh,  g_wh);
    cudaGetSymbolAddress((void**)&p_wl,  g_wl);
    cudaGetSymbolAddress((void**)&p_yh,  g_yh);
    cudaGetSymbolAddress((void**)&p_yl,  g_yl);
    cudaGetSymbolAddress((void**)&p_qh,  g_qh);
    cudaGetSymbolAddress((void**)&p_ql,  g_ql);
    cudaGetSymbolAddress((void**)&p_kh,  g_kh);
    cudaGetSymbolAddress((void**)&p_kl,  g_kl);
    cudaGetSymbolAddress((void**)&p_vh,  g_vh);
    cudaGetSymbolAddress((void**)&p_vl,  g_vl);

    cudaFuncSetAttribute(qkv_kernel, cudaFuncAttributeMaxDynamicSharedMemorySize, GEMM_SMEM);
    cudaFuncSetAttribute(out_kernel, cudaFuncAttributeMaxDynamicSharedMemorySize, GEMM_SMEM);
    cudaFuncSetAttribute(attn_tc,    cudaFuncAttributeMaxDynamicSharedMemorySize, ATTN_SMEM);

    ln_kernel<<<M_, 256>>>(x, gamma, beta, p_xnh, p_xnl);
    wsplit_kernel<<<dim3(DD_/(256*4), 4), 256>>>(Wq, Wk, Wv, Wo, p_wh, p_wl);
    qkv_kernel<<<dim3(D_/128, M_/128, 3), 256, GEMM_SMEM>>>(p_xnh, p_xnl, p_wh, p_wl,
                                                            p_qh, p_ql, p_kh, p_kl, p_vh, p_vl);
    attn_tc<<<dim3(T_/64, H_, B_), 128, ATTN_SMEM>>>(p_qh, p_ql, p_kh, p_kl, p_vh, p_vl,
                                                     rel, p_yh, p_yl);
    out_kernel<<<dim3(D_/128, M_/128), 256, GEMM_SMEM>>>(p_yh, p_yl, p_wh, p_wl, x, out);
}